// round 14
// baseline (speedup 1.0000x reference)
#include <cuda_runtime.h>
#include <cstdint>

#define NROWS 4096
#define DIM   512
#define LAT   128
#define TOPK  16

#define BI 128
#define BJ 128
#define KC 16
#define NCHUNK (DIM / KC)

// -------- scratch (static __device__ arrays; no runtime allocation) --------
__device__ float g_rec_test[NROWS * DIM];
__device__ float g_rec_train[NROWS * DIM];
__device__ float g_xt[DIM * NROWS];              // rec_test^T           [DIM][NROWS]
__device__ float g_yt_gt[DIM * NROWS];           // -(gt_vals)^T         [DIM][NROWS]
__device__ float g_yt_tr[DIM * NROWS];           // -(rec_train)^T       [DIM][NROWS]
__device__ float g_dist[(size_t)NROWS * NROWS];  // 64 MB, reused for both matrices
__device__ float g_pos[NROWS];
__device__ float g_neg[NROWS];

// -------- packed f32x2 helpers --------
__device__ __forceinline__ unsigned long long f2add(unsigned long long a, unsigned long long b) {
    unsigned long long r;
    asm("add.rn.f32x2 %0, %1, %2;" : "=l"(r) : "l"(a), "l"(b));
    return r;
}
__device__ __forceinline__ unsigned long long dup2(float x) {
    unsigned long long r;
    unsigned xi = __float_as_uint(x);
    asm("mov.b64 %0, {%1, %1};" : "=l"(r) : "r"(xi));
    return r;
}

// -------- cp.async helpers (16B) --------
__device__ __forceinline__ void cpa16(void* dst, const void* src) {
    unsigned d = (unsigned)__cvta_generic_to_shared(dst);
    asm volatile("cp.async.cg.shared.global [%0], [%1], 16;" :: "r"(d), "l"(src));
}
__device__ __forceinline__ void cpa_commit() { asm volatile("cp.async.commit_group;"); }
__device__ __forceinline__ void cpa_wait1()  { asm volatile("cp.async.wait_group 1;"); }
__device__ __forceinline__ void cpa_wait0()  { asm volatile("cp.async.wait_group 0;"); }

// ---------------- GEMM: out[row,:] = lat[row,:] @ W + b ----------------
__global__ void gemm_kernel(const float* __restrict__ lat,
                            const float* __restrict__ W,
                            const float* __restrict__ b,
                            float* __restrict__ out) {
    __shared__ float s_lat[LAT];
    int row = blockIdx.x;
    int tx = threadIdx.x;                         // 0..127
    s_lat[tx] = lat[row * LAT + tx];
    __syncthreads();

    float4 acc = *(const float4*)&b[tx * 4];
    const float4* W4 = (const float4*)W;          // [LAT][DIM/4]
    #pragma unroll 8
    for (int l = 0; l < LAT; l++) {
        float a = s_lat[l];
        float4 w = W4[l * (DIM / 4) + tx];
        acc.x += a * w.x; acc.y += a * w.y; acc.z += a * w.z; acc.w += a * w.w;
    }
    *(float4*)&out[(size_t)row * DIM + tx * 4] = acc;
}

// ---------------- tiled transpose: out[d][n] = sgn * in[n][d] ----------------
// in [NROWS][DIM] -> out [DIM][NROWS]; block 32x8, grid (NROWS/32, DIM/32)
__global__ void transpose_kernel(const float* __restrict__ in,
                                 float* __restrict__ out, float sgn) {
    __shared__ float tile[32][33];
    int nb = blockIdx.x * 32;     // row (n) base
    int db = blockIdx.y * 32;     // col (d) base
    int x = threadIdx.x;          // 0..31
    int y = threadIdx.y;          // 0..7
    #pragma unroll
    for (int j = 0; j < 32; j += 8)
        tile[y + j][x] = in[(size_t)(nb + y + j) * DIM + db + x];
    __syncthreads();
    #pragma unroll
    for (int j = 0; j < 32; j += 8)
        out[(size_t)(db + y + j) * NROWS + nb + x] = sgn * tile[x][y + j];
}

// ---------------- L1 cdist: Dout[i,j] = sum_d |X[i,d] - Y[j,d]| ----------------
// Inputs PRE-TRANSPOSED (k-major [DIM][NROWS]) and Y PRE-NEGATED: one 16B
// cp.async per thread per tile, STS inherently conflict-free.
// 3-buffer pipeline, prefetch depth 2 -> EXACTLY ONE __syncthreads per chunk:
// the load for chunk c+2 lands in chunk (c-1)'s slot, which every thread
// finished reading before the sync at the top of iteration c. Compute loop =
// proven R11 form (dup2 in loop, split j-fragment for conflict-free Ys reads).
__global__ __launch_bounds__(512, 2) void dist_kernel(
    const float* __restrict__ XT, const float* __restrict__ YTn,
    float* __restrict__ Dout)
{
    __shared__ __align__(16) float Xs[3][KC][BI];   // 24 KB
    __shared__ __align__(16) float Ys[3][KC][BJ];   // 24 KB

    int t  = threadIdx.x;
    int tx = t & 15;          // j-group: chunks at tx*4 and 64+tx*4
    int ty = t >> 4;          // i-group: 32 groups x 4 rows
    int i0 = blockIdx.y * BI;
    int j0 = blockIdx.x * BJ;

    int lk = t >> 5;          // k-line within chunk (0..15)
    int ls = (t & 31) * 4;    // 16B segment within the 128-float line

    unsigned long long acc[4][4];
    #pragma unroll
    for (int i = 0; i < 4; i++)
        #pragma unroll
        for (int jp = 0; jp < 4; jp++) acc[i][jp] = 0ULL;   // (0.0f, 0.0f)

    auto load_chunk = [&](int c, int buf) {
        size_t k = (size_t)(c * KC + lk);
        cpa16(&Xs[buf][lk][ls], &XT [k * NROWS + i0 + ls]);
        cpa16(&Ys[buf][lk][ls], &YTn[k * NROWS + j0 + ls]);
        cpa_commit();
    };

    // prologue: prefetch chunks 0 and 1
    load_chunk(0, 0);
    load_chunk(1, 1);

    int cb = 0;                                  // slot of chunk c (cycles 0,1,2)
    for (int c = 0; c < NCHUNK; c++) {
        if (c == NCHUNK - 1) cpa_wait0(); else cpa_wait1();   // chunk c landed
        __syncthreads();                         // all threads done with chunk c-1

        if (c + 2 < NCHUNK) {                    // refill chunk (c-1)'s slot
            int nb = cb + 2; if (nb >= 3) nb -= 3;
            load_chunk(c + 2, nb);
        }

        #pragma unroll
        for (int k = 0; k < KC; k++) {
            float4 a0 = *(const float4*)&Xs[cb][k][ty * 4];               // broadcast
            ulonglong2 bq0 = *(const ulonglong2*)&Ys[cb][k][tx * 4];      // conflict-free
            ulonglong2 bq1 = *(const ulonglong2*)&Ys[cb][k][64 + tx * 4]; // conflict-free
            unsigned long long bb[4] = { bq0.x, bq0.y, bq1.x, bq1.y };
            float av[4] = { a0.x, a0.y, a0.z, a0.w };
            #pragma unroll
            for (int i = 0; i < 4; i++) {
                unsigned long long a2 = dup2(av[i]);
                #pragma unroll
                for (int jp = 0; jp < 4; jp++) {
                    unsigned long long d = f2add(a2, bb[jp]);   // (a-b) packed (Y pre-negated)
                    d &= 0x7FFFFFFF7FFFFFFFULL;                 // packed abs (2x LOP3, alu)
                    acc[i][jp] = f2add(acc[i][jp], d);
                }
            }
        }
        // no trailing sync: next iteration's barrier protects slot reuse

        if (++cb == 3) cb = 0;
    }

    // ---- store 4x8 tile: two 16B chunks per row at j = tx*4 and 64+tx*4 ----
    #pragma unroll
    for (int i = 0; i < 4; i++) {
        size_t rowb = (size_t)(i0 + ty * 4 + i) * NROWS + j0;
        ulonglong2 o0 = { acc[i][0], acc[i][1] };
        ulonglong2 o1 = { acc[i][2], acc[i][3] };
        *(ulonglong2*)&Dout[rowb + tx * 4]      = o0;
        *(ulonglong2*)&Dout[rowb + 64 + tx * 4] = o1;
    }
}

// ---------------- per-row top-16 smallest distances -> mean of reciprocals ----------------
// one warp per row; register-resident branch-free sorted insert (static indices),
// 4x float4 per iteration for MLP=4; 32-way shfl merge at the end.
__device__ __forceinline__ void topk_insert(float (&best)[TOPK], float v) {
    if (v < best[TOPK - 1]) {
        #pragma unroll
        for (int i = TOPK - 1; i > 0; i--)
            best[i] = fminf(fmaxf(v, best[i - 1]), best[i]);
        best[0] = fminf(best[0], v);
    }
}

__global__ void topk_kernel(const float* __restrict__ Dmat, float* __restrict__ out) {
    int warp_global = (blockIdx.x * blockDim.x + threadIdx.x) >> 5;
    int lane = threadIdx.x & 31;
    if (warp_global >= NROWS) return;
    const float4* row4 = (const float4*)(Dmat + (size_t)warp_global * NROWS);

    const float INF = __int_as_float(0x7f800000);
    float best[TOPK];
    #pragma unroll
    for (int i = 0; i < TOPK; i++) best[i] = INF;

    for (int c = lane; c < NROWS / 4; c += 128) {
        float4 v0 = row4[c];
        float4 v1 = row4[c + 32];
        float4 v2 = row4[c + 64];
        float4 v3 = row4[c + 96];
        topk_insert(best, v0.x); topk_insert(best, v0.y);
        topk_insert(best, v0.z); topk_insert(best, v0.w);
        topk_insert(best, v1.x); topk_insert(best, v1.y);
        topk_insert(best, v1.z); topk_insert(best, v1.w);
        topk_insert(best, v2.x); topk_insert(best, v2.y);
        topk_insert(best, v2.z); topk_insert(best, v2.w);
        topk_insert(best, v3.x); topk_insert(best, v3.y);
        topk_insert(best, v3.z); topk_insert(best, v3.w);
    }

    // merge 32 sorted ascending lists, extract 16 global smallest
    int h = 0;
    float ssum = 0.f;
    #pragma unroll
    for (int r = 0; r < TOPK; r++) {
        float v = (h < TOPK) ? best[h] : INF;
        float m = v;
        #pragma unroll
        for (int off = 16; off; off >>= 1)
            m = fminf(m, __shfl_xor_sync(0xffffffffu, m, off));
        unsigned bal = __ballot_sync(0xffffffffu, v == m);
        if (lane == (__ffs(bal) - 1)) h++;
        ssum += 1.0f / m;
    }
    if (lane == 0) out[warp_global] = ssum * (1.0f / TOPK);
}

// ---------------- final: huber(relu(neg - pos)).mean() ----------------
__global__ void final_kernel(const float* __restrict__ pos,
                             const float* __restrict__ neg,
                             float* __restrict__ out) {
    __shared__ float sred[256];
    float s = 0.f;
    for (int i = threadIdx.x; i < NROWS; i += 256) {
        float l = neg[i] - pos[i];
        l = fmaxf(l, 0.f);
        float h = (l <= 1.0f) ? 0.5f * l * l : (l - 0.5f);
        s += h;
    }
    sred[threadIdx.x] = s;
    __syncthreads();
    for (int st = 128; st; st >>= 1) {
        if (threadIdx.x < st) sred[threadIdx.x] += sred[threadIdx.x + st];
        __syncthreads();
    }
    if (threadIdx.x == 0) out[0] = sred[0] * (1.0f / NROWS);
}

// ---------------- launch ----------------
extern "C" void kernel_launch(void* const* d_in, const int* in_sizes, int n_in,
                              void* d_out, int out_size) {
    const float* gt_vals      = (const float*)d_in[0];   // [4096, 512]
    const float* train_latent = (const float*)d_in[1];   // [4096, 128]
    const float* test_latent  = (const float*)d_in[2];   // [4096, 128]
    const float* W            = (const float*)d_in[3];   // [128, 512]
    const float* b            = (const float*)d_in[4];   // [512]
    float* out = (float*)d_out;

    float *rec_test, *rec_train, *xt, *yt_gt, *yt_tr, *dist, *pos, *neg;
    cudaGetSymbolAddress((void**)&rec_test,  g_rec_test);
    cudaGetSymbolAddress((void**)&rec_train, g_rec_train);
    cudaGetSymbolAddress((void**)&xt,        g_xt);
    cudaGetSymbolAddress((void**)&yt_gt,     g_yt_gt);
    cudaGetSymbolAddress((void**)&yt_tr,     g_yt_tr);
    cudaGetSymbolAddress((void**)&dist,      g_dist);
    cudaGetSymbolAddress((void**)&pos,       g_pos);
    cudaGetSymbolAddress((void**)&neg,       g_neg);

    // 1) decode both latents
    gemm_kernel<<<NROWS, 128>>>(test_latent,  W, b, rec_test);
    gemm_kernel<<<NROWS, 128>>>(train_latent, W, b, rec_train);

    // 2) pre-transpose (k-major) with Y-side negation
    dim3 tgrid(NROWS / 32, DIM / 32), tblk(32, 8);
    transpose_kernel<<<tgrid, tblk>>>(rec_test,  xt,     1.0f);
    transpose_kernel<<<tgrid, tblk>>>(gt_vals,   yt_gt, -1.0f);
    transpose_kernel<<<tgrid, tblk>>>(rec_train, yt_tr, -1.0f);

    dim3 dgrid(NROWS / BJ, NROWS / BI);

    // 3) positive: cdist(rec_test, gt_vals) -> top-k
    dist_kernel<<<dgrid, 512>>>(xt, yt_gt, dist);
    topk_kernel<<<(NROWS * 32) / 256, 256>>>(dist, pos);

    // 4) negative: cdist(rec_test, rec_train) -> top-k
    dist_kernel<<<dgrid, 512>>>(xt, yt_tr, dist);
    topk_kernel<<<(NROWS * 32) / 256, 256>>>(dist, neg);

    // 5) huber mean
    final_kernel<<<1, 256>>>(pos, neg, out);
}

// round 15
// speedup vs baseline: 1.0069x; 1.0069x over previous
#include <cuda_runtime.h>
#include <cstdint>

#define NROWS 4096
#define DIM   512
#define LAT   128
#define TOPK  16

#define BI 128
#define BJ 128
#define KC 16
#define NCHUNK (DIM / KC)

// -------- scratch (static __device__ arrays; no runtime allocation) --------
__device__ float g_rec_test[NROWS * DIM];
__device__ float g_rec_train[NROWS * DIM];
__device__ float g_xt[DIM * NROWS];              // rec_test^T           [DIM][NROWS]
__device__ float g_yt_gt[DIM * NROWS];           // -(gt_vals)^T         [DIM][NROWS]
__device__ float g_yt_tr[DIM * NROWS];           // -(rec_train)^T      [DIM][NROWS]
__device__ float g_dist1[(size_t)NROWS * NROWS]; // 64 MB (positive)
__device__ float g_dist2[(size_t)NROWS * NROWS]; // 64 MB (negative)
__device__ float g_pos[NROWS];
__device__ float g_neg[NROWS];

// -------- packed f32x2 helpers --------
__device__ __forceinline__ unsigned long long f2add(unsigned long long a, unsigned long long b) {
    unsigned long long r;
    asm("add.rn.f32x2 %0, %1, %2;" : "=l"(r) : "l"(a), "l"(b));
    return r;
}
__device__ __forceinline__ unsigned long long dup2(float x) {
    unsigned long long r;
    unsigned xi = __float_as_uint(x);
    asm("mov.b64 %0, {%1, %1};" : "=l"(r) : "r"(xi));
    return r;
}

// -------- cp.async helpers (16B) --------
__device__ __forceinline__ void cpa16(void* dst, const void* src) {
    unsigned d = (unsigned)__cvta_generic_to_shared(dst);
    asm volatile("cp.async.cg.shared.global [%0], [%1], 16;" :: "r"(d), "l"(src));
}
__device__ __forceinline__ void cpa_commit() { asm volatile("cp.async.commit_group;"); }
__device__ __forceinline__ void cpa_wait1()  { asm volatile("cp.async.wait_group 1;"); }
__device__ __forceinline__ void cpa_wait0()  { asm volatile("cp.async.wait_group 0;"); }

// ---------------- GEMM: out[row,:] = lat[row,:] @ W + b ----------------
__global__ void gemm_kernel(const float* __restrict__ lat,
                            const float* __restrict__ W,
                            const float* __restrict__ b,
                            float* __restrict__ out) {
    __shared__ float s_lat[LAT];
    int row = blockIdx.x;
    int tx = threadIdx.x;                         // 0..127
    s_lat[tx] = lat[row * LAT + tx];
    __syncthreads();

    float4 acc = *(const float4*)&b[tx * 4];
    const float4* W4 = (const float4*)W;          // [LAT][DIM/4]
    #pragma unroll 8
    for (int l = 0; l < LAT; l++) {
        float a = s_lat[l];
        float4 w = W4[l * (DIM / 4) + tx];
        acc.x += a * w.x; acc.y += a * w.y; acc.z += a * w.z; acc.w += a * w.w;
    }
    *(float4*)&out[(size_t)row * DIM + tx * 4] = acc;
}

// ---------------- tiled transpose: out[d][n] = sgn * in[n][d] ----------------
__global__ void transpose_kernel(const float* __restrict__ in,
                                 float* __restrict__ out, float sgn) {
    __shared__ float tile[32][33];
    int nb = blockIdx.x * 32;     // row (n) base
    int db = blockIdx.y * 32;     // col (d) base
    int x = threadIdx.x;          // 0..31
    int y = threadIdx.y;          // 0..7
    #pragma unroll
    for (int j = 0; j < 32; j += 8)
        tile[y + j][x] = in[(size_t)(nb + y + j) * DIM + db + x];
    __syncthreads();
    #pragma unroll
    for (int j = 0; j < 32; j += 8)
        out[(size_t)(db + y + j) * NROWS + nb + x] = sgn * tile[x][y + j];
}

// ---------------- L1 cdist, BOTH matrices in one launch (grid.z selects) ----
// Inputs PRE-TRANSPOSED (k-major [DIM][NROWS]) and Y PRE-NEGATED: one 16B
// cp.async per thread per tile, STS conflict-free. 3-buffer pipeline, one
// __syncthreads per chunk. Compute loop = frozen R11 form. Fusing both
// matrices into one 2048-CTA launch halves the partial-wave tail cost.
__global__ __launch_bounds__(512, 2) void dist_kernel(
    const float* __restrict__ XT,
    const float* __restrict__ YT1, const float* __restrict__ YT2,
    float* __restrict__ D1, float* __restrict__ D2)
{
    __shared__ __align__(16) float Xs[3][KC][BI];   // 24 KB
    __shared__ __align__(16) float Ys[3][KC][BJ];   // 24 KB

    const float* YTn  = blockIdx.z ? YT2 : YT1;
    float*       Dout = blockIdx.z ? D2  : D1;

    int t  = threadIdx.x;
    int tx = t & 15;          // j-group: chunks at tx*4 and 64+tx*4
    int ty = t >> 4;          // i-group: 32 groups x 4 rows
    int i0 = blockIdx.y * BI;
    int j0 = blockIdx.x * BJ;

    int lk = t >> 5;          // k-line within chunk (0..15)
    int ls = (t & 31) * 4;    // 16B segment within the 128-float line

    unsigned long long acc[4][4];
    #pragma unroll
    for (int i = 0; i < 4; i++)
        #pragma unroll
        for (int jp = 0; jp < 4; jp++) acc[i][jp] = 0ULL;   // (0.0f, 0.0f)

    auto load_chunk = [&](int c, int buf) {
        size_t k = (size_t)(c * KC + lk);
        cpa16(&Xs[buf][lk][ls], &XT [k * NROWS + i0 + ls]);
        cpa16(&Ys[buf][lk][ls], &YTn[k * NROWS + j0 + ls]);
        cpa_commit();
    };

    load_chunk(0, 0);
    load_chunk(1, 1);

    int cb = 0;
    for (int c = 0; c < NCHUNK; c++) {
        if (c == NCHUNK - 1) cpa_wait0(); else cpa_wait1();
        __syncthreads();

        if (c + 2 < NCHUNK) {
            int nb = cb + 2; if (nb >= 3) nb -= 3;
            load_chunk(c + 2, nb);
        }

        #pragma unroll
        for (int k = 0; k < KC; k++) {
            float4 a0 = *(const float4*)&Xs[cb][k][ty * 4];               // broadcast
            ulonglong2 bq0 = *(const ulonglong2*)&Ys[cb][k][tx * 4];      // conflict-free
            ulonglong2 bq1 = *(const ulonglong2*)&Ys[cb][k][64 + tx * 4]; // conflict-free
            unsigned long long bb[4] = { bq0.x, bq0.y, bq1.x, bq1.y };
            float av[4] = { a0.x, a0.y, a0.z, a0.w };
            #pragma unroll
            for (int i = 0; i < 4; i++) {
                unsigned long long a2 = dup2(av[i]);
                #pragma unroll
                for (int jp = 0; jp < 4; jp++) {
                    unsigned long long d = f2add(a2, bb[jp]);   // (a-b) packed (Y pre-negated)
                    d &= 0x7FFFFFFF7FFFFFFFULL;                 // packed abs (2x LOP3, alu)
                    acc[i][jp] = f2add(acc[i][jp], d);
                }
            }
        }
        if (++cb == 3) cb = 0;
    }

    #pragma unroll
    for (int i = 0; i < 4; i++) {
        size_t rowb = (size_t)(i0 + ty * 4 + i) * NROWS + j0;
        ulonglong2 o0 = { acc[i][0], acc[i][1] };
        ulonglong2 o1 = { acc[i][2], acc[i][3] };
        *(ulonglong2*)&Dout[rowb + tx * 4]      = o0;
        *(ulonglong2*)&Dout[rowb + 64 + tx * 4] = o1;
    }
}

// ---------------- per-row top-16 -> mean of reciprocals (both matrices) -------
// 2 warps per row (2048 cols each) for 2x parallelism; each warp builds a
// register-resident sorted-16 (branch-free insert, MLP=4 loads), extracts its
// sorted list into smem, then one warp per row merges the 32 candidates.
// grid: (NROWS/4, 2) — y selects matrix/output. block = 256 (8 warps = 4 rows).
__device__ __forceinline__ void topk_insert(float (&best)[TOPK], float v) {
    if (v < best[TOPK - 1]) {
        #pragma unroll
        for (int i = TOPK - 1; i > 0; i--)
            best[i] = fminf(fmaxf(v, best[i - 1]), best[i]);
        best[0] = fminf(best[0], v);
    }
}

__global__ void topk_kernel(const float* __restrict__ D1, const float* __restrict__ D2,
                            float* __restrict__ pos, float* __restrict__ neg) {
    const float* Dmat = blockIdx.y ? D2 : D1;
    float*       out  = blockIdx.y ? neg : pos;

    __shared__ float cand[4][2][TOPK];

    int w    = threadIdx.x >> 5;       // warp 0..7
    int lane = threadIdx.x & 31;
    int rowLocal = w & 3;
    int half     = w >> 2;             // 0 or 1
    int row  = blockIdx.x * 4 + rowLocal;

    const float4* row4 = (const float4*)(Dmat + (size_t)row * NROWS);

    const float INF = __int_as_float(0x7f800000);
    float best[TOPK];
    #pragma unroll
    for (int i = 0; i < TOPK; i++) best[i] = INF;

    // scan this warp's 2048-column half (512 float4 units) with MLP=4
    int cbase = half * 512 + lane;
    #pragma unroll
    for (int it = 0; it < 4; it++) {
        int c = cbase + it * 128;
        float4 v0 = row4[c];
        float4 v1 = row4[c + 32];
        float4 v2 = row4[c + 64];
        float4 v3 = row4[c + 96];
        topk_insert(best, v0.x); topk_insert(best, v0.y);
        topk_insert(best, v0.z); topk_insert(best, v0.w);
        topk_insert(best, v1.x); topk_insert(best, v1.y);
        topk_insert(best, v1.z); topk_insert(best, v1.w);
        topk_insert(best, v2.x); topk_insert(best, v2.y);
        topk_insert(best, v2.z); topk_insert(best, v2.w);
        topk_insert(best, v3.x); topk_insert(best, v3.y);
        topk_insert(best, v3.z); topk_insert(best, v3.w);
    }

    // extract this warp's global sorted-16 into smem
    {
        int h = 0;
        #pragma unroll
        for (int r = 0; r < TOPK; r++) {
            float v = (h < TOPK) ? best[h] : INF;
            float m = v;
            #pragma unroll
            for (int off = 16; off; off >>= 1)
                m = fminf(m, __shfl_xor_sync(0xffffffffu, m, off));
            unsigned bal = __ballot_sync(0xffffffffu, v == m);
            if (lane == (__ffs(bal) - 1)) h++;
            if (lane == 0) cand[rowLocal][half][r] = m;
        }
    }
    __syncthreads();

    // warps 0..3 merge their row's 32 candidates (1 value per lane)
    if (half == 0) {
        float v = cand[rowLocal][lane >> 4][lane & 15];
        float ssum = 0.f;
        #pragma unroll
        for (int r = 0; r < TOPK; r++) {
            float m = v;
            #pragma unroll
            for (int off = 16; off; off >>= 1)
                m = fminf(m, __shfl_xor_sync(0xffffffffu, m, off));
            unsigned bal = __ballot_sync(0xffffffffu, v == m);
            if (lane == (__ffs(bal) - 1)) v = INF;   // remove extracted value
            ssum += 1.0f / m;
        }
        if (lane == 0) out[row] = ssum * (1.0f / TOPK);
    }
}

// ---------------- final: huber(relu(neg - pos)).mean() ----------------
__global__ void final_kernel(const float* __restrict__ pos,
                             const float* __restrict__ neg,
                             float* __restrict__ out) {
    __shared__ float sred[256];
    float s = 0.f;
    for (int i = threadIdx.x; i < NROWS; i += 256) {
        float l = neg[i] - pos[i];
        l = fmaxf(l, 0.f);
        float h = (l <= 1.0f) ? 0.5f * l * l : (l - 0.5f);
        s += h;
    }
    sred[threadIdx.x] = s;
    __syncthreads();
    for (int st = 128; st; st >>= 1) {
        if (threadIdx.x < st) sred[threadIdx.x] += sred[threadIdx.x + st];
        __syncthreads();
    }
    if (threadIdx.x == 0) out[0] = sred[0] * (1.0f / NROWS);
}

// ---------------- launch ----------------
extern "C" void kernel_launch(void* const* d_in, const int* in_sizes, int n_in,
                              void* d_out, int out_size) {
    const float* gt_vals      = (const float*)d_in[0];   // [4096, 512]
    const float* train_latent = (const float*)d_in[1];   // [4096, 128]
    const float* test_latent  = (const float*)d_in[2];   // [4096, 128]
    const float* W            = (const float*)d_in[3];   // [128, 512]
    const float* b            = (const float*)d_in[4];   // [512]
    float* out = (float*)d_out;

    float *rec_test, *rec_train, *xt, *yt_gt, *yt_tr, *d1, *d2, *pos, *neg;
    cudaGetSymbolAddress((void**)&rec_test,  g_rec_test);
    cudaGetSymbolAddress((void**)&rec_train, g_rec_train);
    cudaGetSymbolAddress((void**)&xt,        g_xt);
    cudaGetSymbolAddress((void**)&yt_gt,     g_yt_gt);
    cudaGetSymbolAddress((void**)&yt_tr,     g_yt_tr);
    cudaGetSymbolAddress((void**)&d1,        g_dist1);
    cudaGetSymbolAddress((void**)&d2,        g_dist2);
    cudaGetSymbolAddress((void**)&pos,       g_pos);
    cudaGetSymbolAddress((void**)&neg,       g_neg);

    // 1) decode both latents
    gemm_kernel<<<NROWS, 128>>>(test_latent,  W, b, rec_test);
    gemm_kernel<<<NROWS, 128>>>(train_latent, W, b, rec_train);

    // 2) pre-transpose (k-major) with Y-side negation
    dim3 tgrid(NROWS / 32, DIM / 32), tblk(32, 8);
    transpose_kernel<<<tgrid, tblk>>>(rec_test,  xt,     1.0f);
    transpose_kernel<<<tgrid, tblk>>>(gt_vals,   yt_gt, -1.0f);
    transpose_kernel<<<tgrid, tblk>>>(rec_train, yt_tr, -1.0f);

    // 3) both cdist matrices in ONE launch (grid.z picks matrix)
    dim3 dgrid(NROWS / BJ, NROWS / BI, 2);
    dist_kernel<<<dgrid, 512>>>(xt, yt_gt, yt_tr, d1, d2);

    // 4) both top-k passes in ONE launch (grid.y picks matrix)
    dim3 kgrid(NROWS / 4, 2);
    topk_kernel<<<kgrid, 256>>>(d1, d2, pos, neg);

    // 5) huber mean
    final_kernel<<<1, 256>>>(pos, neg, out);
}